// round 10
// baseline (speedup 1.0000x reference)
#include <cuda_runtime.h>
#include <cuda.h>
#include <cuda_fp16.h>
#include <cstdint>

// out[bn] = A @ x[bn]^T @ B.  R10 = R9 (TMA pipeline, 2a x 4p tiling) with G1
// switched tf32 -> fp16 mma (k-permuted lds.128 + in-register cvt), halving
// tensor-pipe work (the 60% co-leader) and cutting issue count ~35%.
// G1: T[a=64, p=224pad] = sum_c A[a,c] x[p,c]  (K=768, 24 chunks of 32)
// G2: out[a,h] = sum_p T[a,p] B[p,h]           (K=224)
#define P_DIM 196
#define C_DIM 768
#define NCH 24
#define PP 224
#define XST_B (PP * 128)              // 28672 X region per stage (f32, SW128)
#define AST_B (64 * 128)              // 8192  A region per stage
#define STG_B (XST_B + AST_B)         // 36864
#define NST 3
#define STAGES_B (NST * STG_B)        // 110592
#define TPITCH 232                    // halves per T/Bs row
#define OFF_TS 0
#define OFF_BS (64 * TPITCH * 2)      // 29696
#define MB_OFF STAGES_B
#define SMEM_ALLOC (STAGES_B + 64 + 1024)
#define TX_BYTES (P_DIM * 128 + AST_B)   // 33280 per stage

#define DEVINL __device__ __forceinline__

DEVINL uint32_t smem_u32(const void* p) {
    uint32_t a;
    asm("{ .reg .u64 t; cvta.to.shared.u64 t, %1; cvt.u32.u64 %0, t; }" : "=r"(a) : "l"(p));
    return a;
}
DEVINL uint32_t f2h2(float lo, float hi) {
    __half2 h = __floats2half2_rn(lo, hi);
    return *reinterpret_cast<uint32_t*>(&h);
}
DEVINL float4 lds128(uint32_t addr) {
    float4 v;
    asm volatile("ld.shared.v4.f32 {%0,%1,%2,%3}, [%4];"
                 : "=f"(v.x), "=f"(v.y), "=f"(v.z), "=f"(v.w) : "r"(addr));
    return v;
}
DEVINL void ldsm4(uint32_t* r, uint32_t addr) {
    asm volatile("ldmatrix.sync.aligned.m8n8.x4.shared.b16 {%0,%1,%2,%3}, [%4];"
                 : "=r"(r[0]), "=r"(r[1]), "=r"(r[2]), "=r"(r[3]) : "r"(addr));
}
DEVINL void mma16816(float* d, const uint32_t* a, const uint32_t* b) {
    asm volatile("mma.sync.aligned.m16n8k16.row.col.f32.f16.f16.f32 "
                 "{%0,%1,%2,%3}, {%4,%5,%6,%7}, {%8,%9}, {%0,%1,%2,%3};"
                 : "+f"(d[0]), "+f"(d[1]), "+f"(d[2]), "+f"(d[3])
                 : "r"(a[0]), "r"(a[1]), "r"(a[2]), "r"(a[3]), "r"(b[0]), "r"(b[1]));
}

#define MBAR_INIT(a, c) \
    asm volatile("mbarrier.init.shared.b64 [%0], %1;" :: "r"((uint32_t)(a)), "r"((uint32_t)(c)) : "memory")
#define MBAR_EXPECT_TX(a, b) \
    asm volatile("mbarrier.arrive.expect_tx.shared.b64 _, [%0], %1;" :: "r"((uint32_t)(a)), "r"((uint32_t)(b)) : "memory")
#define MBAR_WAIT(a, p) do {                                                              \
    asm volatile("{ .reg .pred P; WL%=:\n\t"                                              \
        "mbarrier.try_wait.parity.acquire.cta.shared::cta.b64 P, [%0], %1, 0x989680;\n\t" \
        "@P bra.uni WD%=;\n\t bra.uni WL%=;\n\t WD%=: }"                                  \
        :: "r"((uint32_t)(a)), "r"((uint32_t)(p)) : "memory");                            \
} while (0)
#define TMA_2D(dst, map, cx, cy, mb) \
    asm volatile("cp.async.bulk.tensor.2d.shared::cta.global.tile.mbarrier::complete_tx::bytes " \
        "[%0], [%1, {%2, %3}], [%4];" \
        :: "r"((uint32_t)(dst)), "l"(map), "r"((int)(cx)), "r"((int)(cy)), "r"((uint32_t)(mb)) : "memory")
#define TMA_3D(dst, map, cx, cy, cz, mb) \
    asm volatile("cp.async.bulk.tensor.3d.shared::cta.global.tile.mbarrier::complete_tx::bytes " \
        "[%0], [%1, {%2, %3, %4}], [%5];" \
        :: "r"((uint32_t)(dst)), "l"(map), "r"((int)(cx)), "r"((int)(cy)), "r"((int)(cz)), "r"((uint32_t)(mb)) : "memory")

__global__ void __launch_bounds__(256, 2) sepnet_tma_kernel(
    const float* __restrict__ Bmat, float* __restrict__ out,
    const __grid_constant__ CUtensorMap tmX,
    const __grid_constant__ CUtensorMap tmA)
{
    extern __shared__ char smem_raw[];
    const uint32_t sb = (smem_u32(smem_raw) + 1023) & ~1023u;
    const int tid = threadIdx.x;
    const int wid = tid >> 5;
    const int lane = tid & 31;
    const int bn = blockIdx.x;

    if (tid == 0)
        for (int s = 0; s < NST; s++) MBAR_INIT(sb + MB_OFF + 8 * s, 1);
    // zero X pad rows (196..223) in all stages
    for (int i = tid; i < NST * 896; i += 256) {
        int s = i / 896, w = i % 896;
        asm volatile("st.shared.b32 [%0], %1;"
            :: "r"(sb + s * STG_B + P_DIM * 128 + w * 4), "r"(0u) : "memory");
    }
    __syncthreads();
    if (tid == 0) {
#pragma unroll
        for (int pre = 0; pre < 2; pre++) {
            uint32_t mb = sb + MB_OFF + 8 * pre;
            MBAR_EXPECT_TX(mb, TX_BYTES);
            TMA_3D(sb + pre * STG_B, &tmX, pre * 32, 0, bn, mb);
            TMA_2D(sb + pre * STG_B + XST_B, &tmA, pre * 32, 0, mb);
        }
    }

    // ---- G1: fp16 mma, warp = (agrp: 32 a-rows) x (pgrp: 56 p-cols, 7 n8-tiles) ----
    // k-permutation within each k16 step (consistent A/B, exact): logical
    // {2q,2q+1,2q+8,2q+9} <-> mem {4q..4q+3} = one 16B chunk per lane.
    float acc[2][7][4];
#pragma unroll
    for (int m = 0; m < 2; m++)
#pragma unroll
        for (int t = 0; t < 7; t++)
            acc[m][t][0] = acc[m][t][1] = acc[m][t][2] = acc[m][t][3] = 0.0f;

    const int abase = (wid & 1) * 32;
    const int pbase = (wid >> 1) * 56;
    const int rr = lane >> 2;            // row-within-8 for both A and X (bases are mult of 8)
    const int q = lane & 3;

    for (int ch = 0; ch < NCH; ch++) {
        const int s = ch % 3;
        const uint32_t ph = (uint32_t)((ch / 3) & 1);
        __syncthreads();
        if (tid == 0 && ch + 2 < NCH) {
            int s2 = (ch + 2) % 3;
            uint32_t mb = sb + MB_OFF + 8 * s2;
            MBAR_EXPECT_TX(mb, TX_BYTES);
            TMA_3D(sb + s2 * STG_B, &tmX, (ch + 2) * 32, 0, bn, mb);
            TMA_2D(sb + s2 * STG_B + XST_B, &tmA, (ch + 2) * 32, 0, mb);
        }
        MBAR_WAIT(sb + MB_OFF + 8 * s, ph);

        const uint32_t Xb = sb + s * STG_B;
        const uint32_t Ab = Xb + XST_B;
#pragma unroll
        for (int ks = 0; ks < 2; ks++) {
            const uint32_t coff = (uint32_t)((4 * ks + q) ^ rr) << 4;
            uint32_t a[2][4];
#pragma unroll
            for (int m = 0; m < 2; m++) {
                float4 va = lds128(Ab + (uint32_t)(abase + m * 16 + rr) * 128 + coff);
                float4 vb = lds128(Ab + (uint32_t)(abase + m * 16 + rr + 8) * 128 + coff);
                a[m][0] = f2h2(va.x, va.y);
                a[m][1] = f2h2(vb.x, vb.y);
                a[m][2] = f2h2(va.z, va.w);
                a[m][3] = f2h2(vb.z, vb.w);
            }
#pragma unroll
            for (int t = 0; t < 7; t++) {
                float4 v = lds128(Xb + (uint32_t)(pbase + t * 8 + rr) * 128 + coff);
                uint32_t b[2];
                b[0] = f2h2(v.x, v.y);
                b[1] = f2h2(v.z, v.w);
                mma16816(acc[0][t], a[0], b);
                mma16816(acc[1][t], a[1], b);
            }
        }
    }

    // ---- T (f16) into alias region (stages 0/1; only stage 2 still being read) ----
    {
        const int cb = pbase + (lane & 3) * 2;
#pragma unroll
        for (int m = 0; m < 2; m++) {
            const int r0 = abase + m * 16 + (lane >> 2);
#pragma unroll
            for (int t = 0; t < 7; t++) {
                int c = cb + t * 8;
                asm volatile("st.shared.b32 [%0], %1;"
                    :: "r"(sb + OFF_TS + (r0 * TPITCH + c) * 2), "r"(f2h2(acc[m][t][0], acc[m][t][1])) : "memory");
                asm volatile("st.shared.b32 [%0], %1;"
                    :: "r"(sb + OFF_TS + ((r0 + 8) * TPITCH + c) * 2), "r"(f2h2(acc[m][t][2], acc[m][t][3])) : "memory");
            }
        }
    }
    // Bs[h][p] f16, pads zero
    for (int i = tid; i < 64 * PP; i += 256) {
        int p = i >> 6, h = i & 63;
        float v = (p < P_DIM) ? Bmat[p * 64 + h] : 0.0f;
        unsigned short hb = __half_as_ushort(__float2half_rn(v));
        asm volatile("st.shared.b16 [%0], %1;"
            :: "r"(sb + OFF_BS + (h * TPITCH + p) * 2), "h"(hb) : "memory");
    }
    __syncthreads();

    // ---- G2: out[a,h] = sum_p T[a,p] Bs[h,p], K = 224, fp16 (R7-proven) ----
    float o[4][4];
#pragma unroll
    for (int i = 0; i < 4; i++)
        o[i][0] = o[i][1] = o[i][2] = o[i][3] = 0.0f;
    const uint32_t tsb = sb + OFF_TS;
    const uint32_t bsb = sb + OFF_BS;
    const int a2row = (wid >> 1) * 16 + (lane & 15);
    const int a2co = (lane & 16) ? 8 : 0;
    const int hhalf = (wid & 1) * 32;
    const int browofs = (lane & 7) + ((lane & 16) >> 1);
    const int bcolofs = ((lane >> 3) & 1) * 8;
#pragma unroll
    for (int ks = 0; ks < 14; ks++) {
        const int k0 = ks * 16;
        uint32_t a[4];
        ldsm4(a, tsb + (a2row * TPITCH + k0 + a2co) * 2);
#pragma unroll
        for (int g = 0; g < 2; g++) {
            uint32_t b[4];
            ldsm4(b, bsb + ((hhalf + g * 16 + browofs) * TPITCH + k0 + bcolofs) * 2);
            mma16816(o[2 * g], a, &b[0]);
            mma16816(o[2 * g + 1], a, &b[2]);
        }
    }
    {
        float* ob = out + (size_t)bn * 4096;
        const int r0 = (wid >> 1) * 16 + lane / 4;
        const int cb = hhalf + (lane & 3) * 2;
#pragma unroll
        for (int nt = 0; nt < 4; nt++) {
            int c = cb + nt * 8;
            *reinterpret_cast<float2*>(ob + r0 * 64 + c) = make_float2(o[nt][0], o[nt][1]);
            *reinterpret_cast<float2*>(ob + (r0 + 8) * 64 + c) = make_float2(o[nt][2], o[nt][3]);
        }
    }
}

extern "C" void kernel_launch(void* const* d_in, const int* in_sizes, int n_in,
                              void* d_out, int out_size) {
    int ix = 0, ia = 1, ib = 2;
    for (int i = 0; i < n_in; i++) {
        if (in_sizes[i] == 237244416) ix = i;
        else if (in_sizes[i] == 49152) ia = i;
        else if (in_sizes[i] == 12544) ib = i;
    }
    void* xp = d_in[ix];
    void* ap = d_in[ia];
    const float* B = (const float*)d_in[ib];
    float* out = (float*)d_out;

    typedef CUresult (CUDAAPI * EncFn)(
        CUtensorMap*, CUtensorMapDataType, cuuint32_t, void*,
        const cuuint64_t*, const cuuint64_t*, const cuuint32_t*, const cuuint32_t*,
        CUtensorMapInterleave, CUtensorMapSwizzle, CUtensorMapL2promotion, CUtensorMapFloatOOBfill);
    void* fnp = nullptr;
    cudaDriverEntryPointQueryResult qr;
    cudaGetDriverEntryPointByVersion("cuTensorMapEncodeTiled", &fnp, 12000,
                                     cudaEnableDefault, &qr);
    EncFn enc = (EncFn)fnp;

    CUtensorMap tmX, tmA;
    {
        cuuint64_t dims[3] = { (cuuint64_t)C_DIM, (cuuint64_t)P_DIM, 1576 };
        cuuint64_t strides[2] = { (cuuint64_t)C_DIM * 4, (cuuint64_t)P_DIM * C_DIM * 4 };
        cuuint32_t box[3] = { 32, (cuuint32_t)P_DIM, 1 };
        cuuint32_t es[3] = { 1, 1, 1 };
        enc(&tmX, CU_TENSOR_MAP_DATA_TYPE_FLOAT32, 3, xp, dims, strides, box, es,
            CU_TENSOR_MAP_INTERLEAVE_NONE, CU_TENSOR_MAP_SWIZZLE_128B,
            CU_TENSOR_MAP_L2_PROMOTION_L2_128B, CU_TENSOR_MAP_FLOAT_OOB_FILL_NONE);
    }
    {
        cuuint64_t dims[2] = { (cuuint64_t)C_DIM, 64 };
        cuuint64_t strides[1] = { (cuuint64_t)C_DIM * 4 };
        cuuint32_t box[2] = { 32, 64 };
        cuuint32_t es[2] = { 1, 1 };
        enc(&tmA, CU_TENSOR_MAP_DATA_TYPE_FLOAT32, 2, ap, dims, strides, box, es,
            CU_TENSOR_MAP_INTERLEAVE_NONE, CU_TENSOR_MAP_SWIZZLE_128B,
            CU_TENSOR_MAP_L2_PROMOTION_L2_128B, CU_TENSOR_MAP_FLOAT_OOB_FILL_NONE);
    }

    cudaFuncSetAttribute(sepnet_tma_kernel,
                         cudaFuncAttributeMaxDynamicSharedMemorySize, SMEM_ALLOC);
    sepnet_tma_kernel<<<1576, 256, SMEM_ALLOC>>>(B, out, tmX, tmA);
}

// round 11
// speedup vs baseline: 1.2210x; 1.2210x over previous
#include <cuda_runtime.h>
#include <cuda.h>
#include <cuda_fp16.h>
#include <cstdint>

// out[bn] = A @ x[bn]^T @ B.  R11 = R10 with the fragment->chunk map fixed for
// conflict-free quarter-warp LDS.128: chunk(ks,q) = 2q+ks (one of each XOR-1
// pair), so rows rr and rr^1 in a quarter-warp hit disjoint bank-group sets.
// G1: T[a=64, p=224pad] = sum_c A[a,c] x[p,c]  (K=768, 24 chunks of 32, fp16 mma)
// G2: out[a,h] = sum_p T[a,p] B[p,h]           (K=224, fp16 mma)
#define P_DIM 196
#define C_DIM 768
#define NCH 24
#define PP 224
#define XST_B (PP * 128)              // 28672 X region per stage (f32, SW128)
#define AST_B (64 * 128)              // 8192  A region per stage
#define STG_B (XST_B + AST_B)         // 36864
#define NST 3
#define STAGES_B (NST * STG_B)        // 110592
#define TPITCH 232                    // halves per T/Bs row
#define OFF_TS 0
#define OFF_BS (64 * TPITCH * 2)      // 29696
#define MB_OFF STAGES_B
#define SMEM_ALLOC (STAGES_B + 64 + 1024)
#define TX_BYTES (P_DIM * 128 + AST_B)   // 33280 per stage

#define DEVINL __device__ __forceinline__

DEVINL uint32_t smem_u32(const void* p) {
    uint32_t a;
    asm("{ .reg .u64 t; cvta.to.shared.u64 t, %1; cvt.u32.u64 %0, t; }" : "=r"(a) : "l"(p));
    return a;
}
DEVINL uint32_t f2h2(float lo, float hi) {
    __half2 h = __floats2half2_rn(lo, hi);
    return *reinterpret_cast<uint32_t*>(&h);
}
DEVINL float4 lds128(uint32_t addr) {
    float4 v;
    asm volatile("ld.shared.v4.f32 {%0,%1,%2,%3}, [%4];"
                 : "=f"(v.x), "=f"(v.y), "=f"(v.z), "=f"(v.w) : "r"(addr));
    return v;
}
DEVINL void ldsm4(uint32_t* r, uint32_t addr) {
    asm volatile("ldmatrix.sync.aligned.m8n8.x4.shared.b16 {%0,%1,%2,%3}, [%4];"
                 : "=r"(r[0]), "=r"(r[1]), "=r"(r[2]), "=r"(r[3]) : "r"(addr));
}
DEVINL void mma16816(float* d, const uint32_t* a, const uint32_t* b) {
    asm volatile("mma.sync.aligned.m16n8k16.row.col.f32.f16.f16.f32 "
                 "{%0,%1,%2,%3}, {%4,%5,%6,%7}, {%8,%9}, {%0,%1,%2,%3};"
                 : "+f"(d[0]), "+f"(d[1]), "+f"(d[2]), "+f"(d[3])
                 : "r"(a[0]), "r"(a[1]), "r"(a[2]), "r"(a[3]), "r"(b[0]), "r"(b[1]));
}

#define MBAR_INIT(a, c) \
    asm volatile("mbarrier.init.shared.b64 [%0], %1;" :: "r"((uint32_t)(a)), "r"((uint32_t)(c)) : "memory")
#define MBAR_EXPECT_TX(a, b) \
    asm volatile("mbarrier.arrive.expect_tx.shared.b64 _, [%0], %1;" :: "r"((uint32_t)(a)), "r"((uint32_t)(b)) : "memory")
#define MBAR_WAIT(a, p) do {                                                              \
    asm volatile("{ .reg .pred P; WL%=:\n\t"                                              \
        "mbarrier.try_wait.parity.acquire.cta.shared::cta.b64 P, [%0], %1, 0x989680;\n\t" \
        "@P bra.uni WD%=;\n\t bra.uni WL%=;\n\t WD%=: }"                                  \
        :: "r"((uint32_t)(a)), "r"((uint32_t)(p)) : "memory");                            \
} while (0)
#define TMA_2D(dst, map, cx, cy, mb) \
    asm volatile("cp.async.bulk.tensor.2d.shared::cta.global.tile.mbarrier::complete_tx::bytes " \
        "[%0], [%1, {%2, %3}], [%4];" \
        :: "r"((uint32_t)(dst)), "l"(map), "r"((int)(cx)), "r"((int)(cy)), "r"((uint32_t)(mb)) : "memory")
#define TMA_3D(dst, map, cx, cy, cz, mb) \
    asm volatile("cp.async.bulk.tensor.3d.shared::cta.global.tile.mbarrier::complete_tx::bytes " \
        "[%0], [%1, {%2, %3, %4}], [%5];" \
        :: "r"((uint32_t)(dst)), "l"(map), "r"((int)(cx)), "r"((int)(cy)), "r"((int)(cz)), "r"((uint32_t)(mb)) : "memory")

__global__ void __launch_bounds__(256, 2) sepnet_tma_kernel(
    const float* __restrict__ Bmat, float* __restrict__ out,
    const __grid_constant__ CUtensorMap tmX,
    const __grid_constant__ CUtensorMap tmA)
{
    extern __shared__ char smem_raw[];
    const uint32_t sb = (smem_u32(smem_raw) + 1023) & ~1023u;
    const int tid = threadIdx.x;
    const int wid = tid >> 5;
    const int lane = tid & 31;
    const int bn = blockIdx.x;

    if (tid == 0)
        for (int s = 0; s < NST; s++) MBAR_INIT(sb + MB_OFF + 8 * s, 1);
    // zero X pad rows (196..223) in all stages
    for (int i = tid; i < NST * 896; i += 256) {
        int s = i / 896, w = i % 896;
        asm volatile("st.shared.b32 [%0], %1;"
            :: "r"(sb + s * STG_B + P_DIM * 128 + w * 4), "r"(0u) : "memory");
    }
    __syncthreads();
    if (tid == 0) {
#pragma unroll
        for (int pre = 0; pre < 2; pre++) {
            uint32_t mb = sb + MB_OFF + 8 * pre;
            MBAR_EXPECT_TX(mb, TX_BYTES);
            TMA_3D(sb + pre * STG_B, &tmX, pre * 32, 0, bn, mb);
            TMA_2D(sb + pre * STG_B + XST_B, &tmA, pre * 32, 0, mb);
        }
    }

    // ---- G1: fp16 mma, warp = (agrp: 32 a-rows) x (pgrp: 56 p-cols, 7 n8-tiles) ----
    // Fragment (ks,q) of both A and X reads memory chunk 2q+ks of its row
    // (physical chunk (2q+ks)^(row&7) after TMA SW128). Any consistent A/B
    // chunk pairing is exact; this one makes every consecutive-8-lane phase
    // hit 8 distinct bank groups.
    float acc[2][7][4];
#pragma unroll
    for (int m = 0; m < 2; m++)
#pragma unroll
        for (int t = 0; t < 7; t++)
            acc[m][t][0] = acc[m][t][1] = acc[m][t][2] = acc[m][t][3] = 0.0f;

    const int abase = (wid & 1) * 32;
    const int pbase = (wid >> 1) * 56;
    const int rr = lane >> 2;            // row-within-8 (bases are multiples of 8)
    const int q = lane & 3;

    for (int ch = 0; ch < NCH; ch++) {
        const int s = ch % 3;
        const uint32_t ph = (uint32_t)((ch / 3) & 1);
        __syncthreads();
        if (tid == 0 && ch + 2 < NCH) {
            int s2 = (ch + 2) % 3;
            uint32_t mb = sb + MB_OFF + 8 * s2;
            MBAR_EXPECT_TX(mb, TX_BYTES);
            TMA_3D(sb + s2 * STG_B, &tmX, (ch + 2) * 32, 0, bn, mb);
            TMA_2D(sb + s2 * STG_B + XST_B, &tmA, (ch + 2) * 32, 0, mb);
        }
        MBAR_WAIT(sb + MB_OFF + 8 * s, ph);

        const uint32_t Xb = sb + s * STG_B;
        const uint32_t Ab = Xb + XST_B;
#pragma unroll
        for (int ks = 0; ks < 2; ks++) {
            const uint32_t coff = (uint32_t)((2 * q + ks) ^ rr) << 4;   // conflict-free map
            uint32_t a[2][4];
#pragma unroll
            for (int m = 0; m < 2; m++) {
                float4 va = lds128(Ab + (uint32_t)(abase + m * 16 + rr) * 128 + coff);
                float4 vb = lds128(Ab + (uint32_t)(abase + m * 16 + rr + 8) * 128 + coff);
                a[m][0] = f2h2(va.x, va.y);
                a[m][1] = f2h2(vb.x, vb.y);
                a[m][2] = f2h2(va.z, va.w);
                a[m][3] = f2h2(vb.z, vb.w);
            }
#pragma unroll
            for (int t = 0; t < 7; t++) {
                float4 v = lds128(Xb + (uint32_t)(pbase + t * 8 + rr) * 128 + coff);
                uint32_t b[2];
                b[0] = f2h2(v.x, v.y);
                b[1] = f2h2(v.z, v.w);
                mma16816(acc[0][t], a[0], b);
                mma16816(acc[1][t], a[1], b);
            }
        }
    }

    // ---- T (f16) into alias region (stages 0/1; only stage 2 still being read) ----
    {
        const int cb = pbase + (lane & 3) * 2;
#pragma unroll
        for (int m = 0; m < 2; m++) {
            const int r0 = abase + m * 16 + (lane >> 2);
#pragma unroll
            for (int t = 0; t < 7; t++) {
                int c = cb + t * 8;
                asm volatile("st.shared.b32 [%0], %1;"
                    :: "r"(sb + OFF_TS + (r0 * TPITCH + c) * 2), "r"(f2h2(acc[m][t][0], acc[m][t][1])) : "memory");
                asm volatile("st.shared.b32 [%0], %1;"
                    :: "r"(sb + OFF_TS + ((r0 + 8) * TPITCH + c) * 2), "r"(f2h2(acc[m][t][2], acc[m][t][3])) : "memory");
            }
        }
    }
    // Bs[h][p] f16, pads zero
    for (int i = tid; i < 64 * PP; i += 256) {
        int p = i >> 6, h = i & 63;
        float v = (p < P_DIM) ? Bmat[p * 64 + h] : 0.0f;
        unsigned short hb = __half_as_ushort(__float2half_rn(v));
        asm volatile("st.shared.b16 [%0], %1;"
            :: "r"(sb + OFF_BS + (h * TPITCH + p) * 2), "h"(hb) : "memory");
    }
    __syncthreads();

    // ---- G2: out[a,h] = sum_p T[a,p] Bs[h,p], K = 224, fp16 (R7-proven) ----
    float o[4][4];
#pragma unroll
    for (int i = 0; i < 4; i++)
        o[i][0] = o[i][1] = o[i][2] = o[i][3] = 0.0f;
    const uint32_t tsb = sb + OFF_TS;
    const uint32_t bsb = sb + OFF_BS;
    const int a2row = (wid >> 1) * 16 + (lane & 15);
    const int a2co = (lane & 16) ? 8 : 0;
    const int hhalf = (wid & 1) * 32;
    const int browofs = (lane & 7) + ((lane & 16) >> 1);
    const int bcolofs = ((lane >> 3) & 1) * 8;
#pragma unroll
    for (int ks = 0; ks < 14; ks++) {
        const int k0 = ks * 16;
        uint32_t a[4];
        ldsm4(a, tsb + (a2row * TPITCH + k0 + a2co) * 2);
#pragma unroll
        for (int g = 0; g < 2; g++) {
            uint32_t b[4];
            ldsm4(b, bsb + ((hhalf + g * 16 + browofs) * TPITCH + k0 + bcolofs) * 2);
            mma16816(o[2 * g], a, &b[0]);
            mma16816(o[2 * g + 1], a, &b[2]);
        }
    }
    {
        float* ob = out + (size_t)bn * 4096;
        const int r0 = (wid >> 1) * 16 + lane / 4;
        const int cb = hhalf + (lane & 3) * 2;
#pragma unroll
        for (int nt = 0; nt < 4; nt++) {
            int c = cb + nt * 8;
            *reinterpret_cast<float2*>(ob + r0 * 64 + c) = make_float2(o[nt][0], o[nt][1]);
            *reinterpret_cast<float2*>(ob + (r0 + 8) * 64 + c) = make_float2(o[nt][2], o[nt][3]);
        }
    }
}

extern "C" void kernel_launch(void* const* d_in, const int* in_sizes, int n_in,
                              void* d_out, int out_size) {
    int ix = 0, ia = 1, ib = 2;
    for (int i = 0; i < n_in; i++) {
        if (in_sizes[i] == 237244416) ix = i;
        else if (in_sizes[i] == 49152) ia = i;
        else if (in_sizes[i] == 12544) ib = i;
    }
    void* xp = d_in[ix];
    void* ap = d_in[ia];
    const float* B = (const float*)d_in[ib];
    float* out = (float*)d_out;

    typedef CUresult (CUDAAPI * EncFn)(
        CUtensorMap*, CUtensorMapDataType, cuuint32_t, void*,
        const cuuint64_t*, const cuuint64_t*, const cuuint32_t*, const cuuint32_t*,
        CUtensorMapInterleave, CUtensorMapSwizzle, CUtensorMapL2promotion, CUtensorMapFloatOOBfill);
    void* fnp = nullptr;
    cudaDriverEntryPointQueryResult qr;
    cudaGetDriverEntryPointByVersion("cuTensorMapEncodeTiled", &fnp, 12000,
                                     cudaEnableDefault, &qr);
    EncFn enc = (EncFn)fnp;

    CUtensorMap tmX, tmA;
    {
        cuuint64_t dims[3] = { (cuuint64_t)C_DIM, (cuuint64_t)P_DIM, 1576 };
        cuuint64_t strides[2] = { (cuuint64_t)C_DIM * 4, (cuuint64_t)P_DIM * C_DIM * 4 };
        cuuint32_t box[3] = { 32, (cuuint32_t)P_DIM, 1 };
        cuuint32_t es[3] = { 1, 1, 1 };
        enc(&tmX, CU_TENSOR_MAP_DATA_TYPE_FLOAT32, 3, xp, dims, strides, box, es,
            CU_TENSOR_MAP_INTERLEAVE_NONE, CU_TENSOR_MAP_SWIZZLE_128B,
            CU_TENSOR_MAP_L2_PROMOTION_L2_128B, CU_TENSOR_MAP_FLOAT_OOB_FILL_NONE);
    }
    {
        cuuint64_t dims[2] = { (cuuint64_t)C_DIM, 64 };
        cuuint64_t strides[1] = { (cuuint64_t)C_DIM * 4 };
        cuuint32_t box[2] = { 32, 64 };
        cuuint32_t es[2] = { 1, 1 };
        enc(&tmA, CU_TENSOR_MAP_DATA_TYPE_FLOAT32, 2, ap, dims, strides, box, es,
            CU_TENSOR_MAP_INTERLEAVE_NONE, CU_TENSOR_MAP_SWIZZLE_128B,
            CU_TENSOR_MAP_L2_PROMOTION_L2_128B, CU_TENSOR_MAP_FLOAT_OOB_FILL_NONE);
    }

    cudaFuncSetAttribute(sepnet_tma_kernel,
                         cudaFuncAttributeMaxDynamicSharedMemorySize, SMEM_ALLOC);
    sepnet_tma_kernel<<<1576, 256, SMEM_ALLOC>>>(B, out, tmX, tmA);
}

// round 13
// speedup vs baseline: 1.2338x; 1.0105x over previous
#include <cuda_runtime.h>
#include <cuda.h>
#include <cuda_fp16.h>
#include <cstdint>

// out[bn] = A @ x[bn]^T @ B.  R12 = R11 + A pre-converted to f16 in GMEM
// (TMA f16, SWIZZLE_NONE, 64B rows): A-fragments via 2 lds.128 per m-tile per
// chunk (both k-steps), zero A-side cvts. G1 crossbar -18%, instrs -12/warp/chunk.
// G1: T[a=64, p=224pad] = sum_c A[a,c] x[p,c]  (K=768, 24 chunks of 32, fp16 mma)
// G2: out[a,h] = sum_p T[a,p] B[p,h]           (K=224, fp16 mma)
#define P_DIM 196
#define C_DIM 768
#define NCH 24
#define PP 224
#define XST_B (PP * 128)              // 28672 X region per stage (f32, SW128)
#define AST_B (64 * 64)               // 4096  A region per stage (f16, 64B rows)
#define STG_B (XST_B + AST_B)         // 32768
#define NST 3
#define STAGES_B (NST * STG_B)        // 98304
#define TPITCH 232                    // halves per T/Bs row
#define OFF_TS 0
#define OFF_BS (64 * TPITCH * 2)      // 29696
#define MB_OFF STAGES_B
#define SMEM_ALLOC (STAGES_B + 64 + 1024)
#define TX_BYTES (P_DIM * 128 + AST_B)   // 29184 per stage

#define DEVINL __device__ __forceinline__

__device__ __half g_Ah[64 * C_DIM];   // A pre-rounded to f16 (RN)

DEVINL uint32_t smem_u32(const void* p) {
    uint32_t a;
    asm("{ .reg .u64 t; cvta.to.shared.u64 t, %1; cvt.u32.u64 %0, t; }" : "=r"(a) : "l"(p));
    return a;
}
DEVINL uint32_t f2h2(float lo, float hi) {
    __half2 h = __floats2half2_rn(lo, hi);
    return *reinterpret_cast<uint32_t*>(&h);
}
DEVINL float4 lds128(uint32_t addr) {
    float4 v;
    asm volatile("ld.shared.v4.f32 {%0,%1,%2,%3}, [%4];"
                 : "=f"(v.x), "=f"(v.y), "=f"(v.z), "=f"(v.w) : "r"(addr));
    return v;
}
DEVINL void lds128u(uint32_t* r, uint32_t addr) {
    asm volatile("ld.shared.v4.b32 {%0,%1,%2,%3}, [%4];"
                 : "=r"(r[0]), "=r"(r[1]), "=r"(r[2]), "=r"(r[3]) : "r"(addr));
}
DEVINL void ldsm4(uint32_t* r, uint32_t addr) {
    asm volatile("ldmatrix.sync.aligned.m8n8.x4.shared.b16 {%0,%1,%2,%3}, [%4];"
                 : "=r"(r[0]), "=r"(r[1]), "=r"(r[2]), "=r"(r[3]) : "r"(addr));
}
DEVINL void mma16816(float* d, uint32_t a0, uint32_t a1, uint32_t a2, uint32_t a3,
                     uint32_t b0, uint32_t b1) {
    asm volatile("mma.sync.aligned.m16n8k16.row.col.f32.f16.f16.f32 "
                 "{%0,%1,%2,%3}, {%4,%5,%6,%7}, {%8,%9}, {%0,%1,%2,%3};"
                 : "+f"(d[0]), "+f"(d[1]), "+f"(d[2]), "+f"(d[3])
                 : "r"(a0), "r"(a1), "r"(a2), "r"(a3), "r"(b0), "r"(b1));
}

#define MBAR_INIT(a, c) \
    asm volatile("mbarrier.init.shared.b64 [%0], %1;" :: "r"((uint32_t)(a)), "r"((uint32_t)(c)) : "memory")
#define MBAR_EXPECT_TX(a, b) \
    asm volatile("mbarrier.arrive.expect_tx.shared.b64 _, [%0], %1;" :: "r"((uint32_t)(a)), "r"((uint32_t)(b)) : "memory")
#define MBAR_WAIT(a, p) do {                                                              \
    asm volatile("{ .reg .pred P; WL%=:\n\t"                                              \
        "mbarrier.try_wait.parity.acquire.cta.shared::cta.b64 P, [%0], %1, 0x989680;\n\t" \
        "@P bra.uni WD%=;\n\t bra.uni WL%=;\n\t WD%=: }"                                  \
        :: "r"((uint32_t)(a)), "r"((uint32_t)(p)) : "memory");                            \
} while (0)
#define TMA_2D(dst, map, cx, cy, mb) \
    asm volatile("cp.async.bulk.tensor.2d.shared::cta.global.tile.mbarrier::complete_tx::bytes " \
        "[%0], [%1, {%2, %3}], [%4];" \
        :: "r"((uint32_t)(dst)), "l"(map), "r"((int)(cx)), "r"((int)(cy)), "r"((uint32_t)(mb)) : "memory")
#define TMA_3D(dst, map, cx, cy, cz, mb) \
    asm volatile("cp.async.bulk.tensor.3d.shared::cta.global.tile.mbarrier::complete_tx::bytes " \
        "[%0], [%1, {%2, %3, %4}], [%5];" \
        :: "r"((uint32_t)(dst)), "l"(map), "r"((int)(cx)), "r"((int)(cy)), "r"((int)(cz)), "r"((uint32_t)(mb)) : "memory")

__global__ void cvt_A_kernel(const float* __restrict__ A) {
    int i = blockIdx.x * 256 + threadIdx.x;
    if (i < 64 * C_DIM) g_Ah[i] = __float2half_rn(A[i]);
}

__global__ void __launch_bounds__(256, 2) sepnet_tma_kernel(
    const float* __restrict__ Bmat, float* __restrict__ out,
    const __grid_constant__ CUtensorMap tmX,
    const __grid_constant__ CUtensorMap tmA)
{
    extern __shared__ char smem_raw[];
    const uint32_t sb = (smem_u32(smem_raw) + 1023) & ~1023u;
    const int tid = threadIdx.x;
    const int wid = tid >> 5;
    const int lane = tid & 31;
    const int bn = blockIdx.x;

    if (tid == 0)
        for (int s = 0; s < NST; s++) MBAR_INIT(sb + MB_OFF + 8 * s, 1);
    // zero X pad rows (196..223) in all stages
    for (int i = tid; i < NST * 896; i += 256) {
        int s = i / 896, w = i % 896;
        asm volatile("st.shared.b32 [%0], %1;"
            :: "r"(sb + s * STG_B + P_DIM * 128 + w * 4), "r"(0u) : "memory");
    }
    __syncthreads();
    if (tid == 0) {
#pragma unroll
        for (int pre = 0; pre < 2; pre++) {
            uint32_t mb = sb + MB_OFF + 8 * pre;
            MBAR_EXPECT_TX(mb, TX_BYTES);
            TMA_3D(sb + pre * STG_B, &tmX, pre * 32, 0, bn, mb);
            TMA_2D(sb + pre * STG_B + XST_B, &tmA, pre * 32, 0, mb);
        }
    }

    // ---- G1: fp16 mma, warp = (agrp: 32 a-rows) x (pgrp: 56 p-cols) ----
    // k-map: fragment (ks,q) <-> mem c {8q+4ks .. +3}. X: physical chunk
    // (2q+ks)^rr (SW128). A (f16, no swizzle): one lds.128 per row gives
    // halves {8q..8q+7} = both ks steps.
    float acc[2][7][4];
#pragma unroll
    for (int m = 0; m < 2; m++)
#pragma unroll
        for (int t = 0; t < 7; t++)
            acc[m][t][0] = acc[m][t][1] = acc[m][t][2] = acc[m][t][3] = 0.0f;

    const int abase = (wid & 1) * 32;
    const int pbase = (wid >> 1) * 56;
    const int rr = lane >> 2;            // row-within-8 (bases are multiples of 8)
    const int q = lane & 3;

    for (int ch = 0; ch < NCH; ch++) {
        const int s = ch % 3;
        const uint32_t ph = (uint32_t)((ch / 3) & 1);
        __syncthreads();
        if (tid == 0 && ch + 2 < NCH) {
            int s2 = (ch + 2) % 3;
            uint32_t mb = sb + MB_OFF + 8 * s2;
            MBAR_EXPECT_TX(mb, TX_BYTES);
            TMA_3D(sb + s2 * STG_B, &tmX, (ch + 2) * 32, 0, bn, mb);
            TMA_2D(sb + s2 * STG_B + XST_B, &tmA, (ch + 2) * 32, 0, mb);
        }
        MBAR_WAIT(sb + MB_OFF + 8 * s, ph);

        const uint32_t Xb = sb + s * STG_B;
        const uint32_t Ab = Xb + XST_B;
        // A-fragments for both ks: rows abase+m*16+rr and +8, 16B each
        uint32_t alo[2][4], ahi[2][4];
#pragma unroll
        for (int m = 0; m < 2; m++) {
            lds128u(alo[m], Ab + (uint32_t)(abase + m * 16 + rr) * 64 + (uint32_t)q * 16);
            lds128u(ahi[m], Ab + (uint32_t)(abase + m * 16 + rr + 8) * 64 + (uint32_t)q * 16);
        }
#pragma unroll
        for (int ks = 0; ks < 2; ks++) {
            const uint32_t coff = (uint32_t)((2 * q + ks) ^ rr) << 4;
#pragma unroll
            for (int t = 0; t < 7; t++) {
                float4 v = lds128(Xb + (uint32_t)(pbase + t * 8 + rr) * 128 + coff);
                uint32_t b0 = f2h2(v.x, v.y);
                uint32_t b1 = f2h2(v.z, v.w);
                mma16816(acc[0][t], alo[0][2 * ks], ahi[0][2 * ks],
                         alo[0][2 * ks + 1], ahi[0][2 * ks + 1], b0, b1);
                mma16816(acc[1][t], alo[1][2 * ks], ahi[1][2 * ks],
                         alo[1][2 * ks + 1], ahi[1][2 * ks + 1], b0, b1);
            }
        }
    }

    // ---- T (f16) into alias region (stages 0/1; only stage 2 still being read) ----
    {
        const int cb = pbase + (lane & 3) * 2;
#pragma unroll
        for (int m = 0; m < 2; m++) {
            const int r0 = abase + m * 16 + (lane >> 2);
#pragma unroll
            for (int t = 0; t < 7; t++) {
                int c = cb + t * 8;
                asm volatile("st.shared.b32 [%0], %1;"
                    :: "r"(sb + OFF_TS + (r0 * TPITCH + c) * 2), "r"(f2h2(acc[m][t][0], acc[m][t][1])) : "memory");
                asm volatile("st.shared.b32 [%0], %1;"
                    :: "r"(sb + OFF_TS + ((r0 + 8) * TPITCH + c) * 2), "r"(f2h2(acc[m][t][2], acc[m][t][3])) : "memory");
            }
        }
    }
    // Bs[h][p] f16, pads zero
    for (int i = tid; i < 64 * PP; i += 256) {
        int p = i >> 6, h = i & 63;
        float v = (p < P_DIM) ? Bmat[p * 64 + h] : 0.0f;
        unsigned short hb = __half_as_ushort(__float2half_rn(v));
        asm volatile("st.shared.b16 [%0], %1;"
            :: "r"(sb + OFF_BS + (h * TPITCH + p) * 2), "h"(hb) : "memory");
    }
    __syncthreads();

    // ---- G2: out[a,h] = sum_p T[a,p] Bs[h,p], K = 224, fp16 (R7-proven) ----
    float o[4][4];
#pragma unroll
    for (int i = 0; i < 4; i++)
        o[i][0] = o[i][1] = o[i][2] = o[i][3] = 0.0f;
    const uint32_t tsb = sb + OFF_TS;
    const uint32_t bsb = sb + OFF_BS;
    const int a2row = (wid >> 1) * 16 + (lane & 15);
    const int a2co = (lane & 16) ? 8 : 0;
    const int hhalf = (wid & 1) * 32;
    const int browofs = (lane & 7) + ((lane & 16) >> 1);
    const int bcolofs = ((lane >> 3) & 1) * 8;
#pragma unroll
    for (int ks = 0; ks < 14; ks++) {
        const int k0 = ks * 16;
        uint32_t a[4];
        ldsm4(a, tsb + (a2row * TPITCH + k0 + a2co) * 2);
#pragma unroll
        for (int g = 0; g < 2; g++) {
            uint32_t b[4];
            ldsm4(b, bsb + ((hhalf + g * 16 + browofs) * TPITCH + k0 + bcolofs) * 2);
            mma16816(o[2 * g], a[0], a[1], a[2], a[3], b[0], b[1]);
            mma16816(o[2 * g + 1], a[0], a[1], a[2], a[3], b[2], b[3]);
        }
    }
    {
        float* ob = out + (size_t)bn * 4096;
        const int r0 = (wid >> 1) * 16 + lane / 4;
        const int cb = hhalf + (lane & 3) * 2;
#pragma unroll
        for (int nt = 0; nt < 4; nt++) {
            int c = cb + nt * 8;
            *reinterpret_cast<float2*>(ob + r0 * 64 + c) = make_float2(o[nt][0], o[nt][1]);
            *reinterpret_cast<float2*>(ob + (r0 + 8) * 64 + c) = make_float2(o[nt][2], o[nt][3]);
        }
    }
}

extern "C" void kernel_launch(void* const* d_in, const int* in_sizes, int n_in,
                              void* d_out, int out_size) {
    int ix = 0, ia = 1, ib = 2;
    for (int i = 0; i < n_in; i++) {
        if (in_sizes[i] == 237244416) ix = i;
        else if (in_sizes[i] == 49152) ia = i;
        else if (in_sizes[i] == 12544) ib = i;
    }
    void* xp = d_in[ix];
    const float* A = (const float*)d_in[ia];
    const float* B = (const float*)d_in[ib];
    float* out = (float*)d_out;

    void* ah_ptr = nullptr;
    cudaGetSymbolAddress(&ah_ptr, g_Ah);

    typedef CUresult (CUDAAPI * EncFn)(
        CUtensorMap*, CUtensorMapDataType, cuuint32_t, void*,
        const cuuint64_t*, const cuuint64_t*, const cuuint32_t*, const cuuint32_t*,
        CUtensorMapInterleave, CUtensorMapSwizzle, CUtensorMapL2promotion, CUtensorMapFloatOOBfill);
    void* fnp = nullptr;
    cudaDriverEntryPointQueryResult qr;
    cudaGetDriverEntryPointByVersion("cuTensorMapEncodeTiled", &fnp, 12000,
                                     cudaEnableDefault, &qr);
    EncFn enc = (EncFn)fnp;

    CUtensorMap tmX, tmA;
    {
        cuuint64_t dims[3] = { (cuuint64_t)C_DIM, (cuuint64_t)P_DIM, 1576 };
        cuuint64_t strides[2] = { (cuuint64_t)C_DIM * 4, (cuuint64_t)P_DIM * C_DIM * 4 };
        cuuint32_t box[3] = { 32, (cuuint32_t)P_DIM, 1 };
        cuuint32_t es[3] = { 1, 1, 1 };
        enc(&tmX, CU_TENSOR_MAP_DATA_TYPE_FLOAT32, 3, xp, dims, strides, box, es,
            CU_TENSOR_MAP_INTERLEAVE_NONE, CU_TENSOR_MAP_SWIZZLE_128B,
            CU_TENSOR_MAP_L2_PROMOTION_L2_128B, CU_TENSOR_MAP_FLOAT_OOB_FILL_NONE);
    }
    {
        cuuint64_t dims[2] = { (cuuint64_t)C_DIM, 64 };
        cuuint64_t strides[1] = { (cuuint64_t)C_DIM * 2 };
        cuuint32_t box[2] = { 32, 64 };
        cuuint32_t es[2] = { 1, 1 };
        enc(&tmA, CU_TENSOR_MAP_DATA_TYPE_FLOAT16, 2, ah_ptr, dims, strides, box, es,
            CU_TENSOR_MAP_INTERLEAVE_NONE, CU_TENSOR_MAP_SWIZZLE_NONE,
            CU_TENSOR_MAP_L2_PROMOTION_L2_128B, CU_TENSOR_MAP_FLOAT_OOB_FILL_NONE);
    }

    cvt_A_kernel<<<(64 * C_DIM + 255) / 256, 256>>>(A);
    cudaFuncSetAttribute(sepnet_tma_kernel,
                         cudaFuncAttributeMaxDynamicSharedMemorySize, SMEM_ALLOC);
    sepnet_tma_kernel<<<1576, 256, SMEM_ALLOC>>>(B, out, tmX, tmA);
}

// round 14
// speedup vs baseline: 1.2519x; 1.0147x over previous
#include <cuda_runtime.h>
#include <cuda.h>
#include <cuda_fp16.h>
#include <cstdint>

// out[bn] = A @ x[bn]^T @ B.  R14 = R13 with the per-chunk __syncthreads
// replaced by a full/empty mbarrier pipeline (decoupled warps): smooth DRAM
// duty instead of barrier-quantized bursts.
// G1: T[a=64, p=224pad] = sum_c A[a,c] x[p,c]  (K=768, 24 chunks of 32, fp16 mma)
// G2: out[a,h] = sum_p T[a,p] B[p,h]           (K=224, fp16 mma)
#define P_DIM 196
#define C_DIM 768
#define NCH 24
#define PP 224
#define XST_B (PP * 128)              // 28672 X region per stage (f32, SW128)
#define AST_B (64 * 64)               // 4096  A region per stage (f16, 64B rows)
#define STG_B (XST_B + AST_B)         // 32768
#define NST 3
#define STAGES_B (NST * STG_B)        // 98304
#define TPITCH 232                    // halves per T/Bs row
#define OFF_TS 0
#define OFF_BS (64 * TPITCH * 2)      // 29696
#define MB_OFF STAGES_B               // full[0..2] at +0,8,16; empty[0..2] at +24,32,40
#define SMEM_ALLOC (STAGES_B + 64 + 1024)
#define TX_BYTES (P_DIM * 128 + AST_B)   // 29184 per stage

#define DEVINL __device__ __forceinline__

__device__ __half g_Ah[64 * C_DIM];   // A pre-rounded to f16 (RN)

DEVINL uint32_t smem_u32(const void* p) {
    uint32_t a;
    asm("{ .reg .u64 t; cvta.to.shared.u64 t, %1; cvt.u32.u64 %0, t; }" : "=r"(a) : "l"(p));
    return a;
}
DEVINL uint32_t f2h2(float lo, float hi) {
    __half2 h = __floats2half2_rn(lo, hi);
    return *reinterpret_cast<uint32_t*>(&h);
}
DEVINL float4 lds128(uint32_t addr) {
    float4 v;
    asm volatile("ld.shared.v4.f32 {%0,%1,%2,%3}, [%4];"
                 : "=f"(v.x), "=f"(v.y), "=f"(v.z), "=f"(v.w) : "r"(addr));
    return v;
}
DEVINL void lds128u(uint32_t* r, uint32_t addr) {
    asm volatile("ld.shared.v4.b32 {%0,%1,%2,%3}, [%4];"
                 : "=r"(r[0]), "=r"(r[1]), "=r"(r[2]), "=r"(r[3]) : "r"(addr));
}
DEVINL void ldsm4(uint32_t* r, uint32_t addr) {
    asm volatile("ldmatrix.sync.aligned.m8n8.x4.shared.b16 {%0,%1,%2,%3}, [%4];"
                 : "=r"(r[0]), "=r"(r[1]), "=r"(r[2]), "=r"(r[3]) : "r"(addr));
}
DEVINL void mma16816(float* d, uint32_t a0, uint32_t a1, uint32_t a2, uint32_t a3,
                     uint32_t b0, uint32_t b1) {
    asm volatile("mma.sync.aligned.m16n8k16.row.col.f32.f16.f16.f32 "
                 "{%0,%1,%2,%3}, {%4,%5,%6,%7}, {%8,%9}, {%0,%1,%2,%3};"
                 : "+f"(d[0]), "+f"(d[1]), "+f"(d[2]), "+f"(d[3])
                 : "r"(a0), "r"(a1), "r"(a2), "r"(a3), "r"(b0), "r"(b1));
}

#define MBAR_INIT(a, c) \
    asm volatile("mbarrier.init.shared.b64 [%0], %1;" :: "r"((uint32_t)(a)), "r"((uint32_t)(c)) : "memory")
#define MBAR_EXPECT_TX(a, b) \
    asm volatile("mbarrier.arrive.expect_tx.shared.b64 _, [%0], %1;" :: "r"((uint32_t)(a)), "r"((uint32_t)(b)) : "memory")
#define MBAR_ARRIVE(a) \
    asm volatile("mbarrier.arrive.shared.b64 _, [%0];" :: "r"((uint32_t)(a)) : "memory")
#define MBAR_WAIT(a, p) do {                                                              \
    asm volatile("{ .reg .pred P; WL%=:\n\t"                                              \
        "mbarrier.try_wait.parity.acquire.cta.shared::cta.b64 P, [%0], %1, 0x989680;\n\t" \
        "@P bra.uni WD%=;\n\t bra.uni WL%=;\n\t WD%=: }"                                  \
        :: "r"((uint32_t)(a)), "r"((uint32_t)(p)) : "memory");                            \
} while (0)
#define MBAR_WAIT_RLX(a, p) do {                                                          \
    asm volatile("{ .reg .pred P; WL%=:\n\t"                                              \
        "mbarrier.try_wait.parity.relaxed.cta.shared::cta.b64 P, [%0], %1, 0x989680;\n\t" \
        "@P bra.uni WD%=;\n\t bra.uni WL%=;\n\t WD%=: }"                                  \
        :: "r"((uint32_t)(a)), "r"((uint32_t)(p)) : "memory");                            \
} while (0)
#define TMA_2D(dst, map, cx, cy, mb) \
    asm volatile("cp.async.bulk.tensor.2d.shared::cta.global.tile.mbarrier::complete_tx::bytes " \
        "[%0], [%1, {%2, %3}], [%4];" \
        :: "r"((uint32_t)(dst)), "l"(map), "r"((int)(cx)), "r"((int)(cy)), "r"((uint32_t)(mb)) : "memory")
#define TMA_3D(dst, map, cx, cy, cz, mb) \
    asm volatile("cp.async.bulk.tensor.3d.shared::cta.global.tile.mbarrier::complete_tx::bytes " \
        "[%0], [%1, {%2, %3, %4}], [%5];" \
        :: "r"((uint32_t)(dst)), "l"(map), "r"((int)(cx)), "r"((int)(cy)), "r"((int)(cz)), "r"((uint32_t)(mb)) : "memory")

__global__ void cvt_A_kernel(const float* __restrict__ A) {
    int i = blockIdx.x * 256 + threadIdx.x;
    if (i < 64 * C_DIM) g_Ah[i] = __float2half_rn(A[i]);
}

__global__ void __launch_bounds__(256, 2) sepnet_tma_kernel(
    const float* __restrict__ Bmat, float* __restrict__ out,
    const __grid_constant__ CUtensorMap tmX,
    const __grid_constant__ CUtensorMap tmA)
{
    extern __shared__ char smem_raw[];
    const uint32_t sb = (smem_u32(smem_raw) + 1023) & ~1023u;
    const int tid = threadIdx.x;
    const int wid = tid >> 5;
    const int lane = tid & 31;
    const int bn = blockIdx.x;

    if (tid == 0) {
        for (int s = 0; s < NST; s++) {
            MBAR_INIT(sb + MB_OFF + 8 * s, 1);         // full: TMA tx
            MBAR_INIT(sb + MB_OFF + 24 + 8 * s, 256);  // empty: all threads arrive
        }
    }
    // zero X pad rows (196..223) in all stages
    for (int i = tid; i < NST * 896; i += 256) {
        int s = i / 896, w = i % 896;
        asm volatile("st.shared.b32 [%0], %1;"
            :: "r"(sb + s * STG_B + P_DIM * 128 + w * 4), "r"(0u) : "memory");
    }
    __syncthreads();
    if (tid == 0) {
#pragma unroll
        for (int pre = 0; pre < 2; pre++) {
            uint32_t mb = sb + MB_OFF + 8 * pre;
            MBAR_EXPECT_TX(mb, TX_BYTES);
            TMA_3D(sb + pre * STG_B, &tmX, pre * 32, 0, bn, mb);
            TMA_2D(sb + pre * STG_B + XST_B, &tmA, pre * 32, 0, mb);
        }
    }

    // ---- G1: fp16 mma, warp = (agrp: 32 a-rows) x (pgrp: 56 p-cols) ----
    float acc[2][7][4];
#pragma unroll
    for (int m = 0; m < 2; m++)
#pragma unroll
        for (int t = 0; t < 7; t++)
            acc[m][t][0] = acc[m][t][1] = acc[m][t][2] = acc[m][t][3] = 0.0f;

    const int abase = (wid & 1) * 32;
    const int pbase = (wid >> 1) * 56;
    const int rr = lane >> 2;
    const int q = lane & 3;

    for (int ch = 0; ch < NCH; ch++) {
        const int s = ch % 3;
        const uint32_t ph = (uint32_t)((ch / 3) & 1);

        // producer: issue chunk ch+2 into stage (ch+2)%3 once its consumers drained
        if (tid == 0 && ch + 2 < NCH) {
            const int c2 = ch + 2, s2 = c2 % 3;
            if (c2 >= NST) MBAR_WAIT_RLX(sb + MB_OFF + 24 + 8 * s2, (uint32_t)(((c2 / 3) - 1) & 1));
            uint32_t mb = sb + MB_OFF + 8 * s2;
            MBAR_EXPECT_TX(mb, TX_BYTES);
            TMA_3D(sb + s2 * STG_B, &tmX, c2 * 32, 0, bn, mb);
            TMA_2D(sb + s2 * STG_B + XST_B, &tmA, c2 * 32, 0, mb);
        }

        MBAR_WAIT(sb + MB_OFF + 8 * s, ph);

        const uint32_t Xb = sb + s * STG_B;
        const uint32_t Ab = Xb + XST_B;
        uint32_t alo[2][4], ahi[2][4];
#pragma unroll
        for (int m = 0; m < 2; m++) {
            lds128u(alo[m], Ab + (uint32_t)(abase + m * 16 + rr) * 64 + (uint32_t)q * 16);
            lds128u(ahi[m], Ab + (uint32_t)(abase + m * 16 + rr + 8) * 64 + (uint32_t)q * 16);
        }
#pragma unroll
        for (int ks = 0; ks < 2; ks++) {
            const uint32_t coff = (uint32_t)((2 * q + ks) ^ rr) << 4;
#pragma unroll
            for (int t = 0; t < 7; t++) {
                float4 v = lds128(Xb + (uint32_t)(pbase + t * 8 + rr) * 128 + coff);
                uint32_t b0 = f2h2(v.x, v.y);
                uint32_t b1 = f2h2(v.z, v.w);
                mma16816(acc[0][t], alo[0][2 * ks], ahi[0][2 * ks],
                         alo[0][2 * ks + 1], ahi[0][2 * ks + 1], b0, b1);
                mma16816(acc[1][t], alo[1][2 * ks], ahi[1][2 * ks],
                         alo[1][2 * ks + 1], ahi[1][2 * ks + 1], b0, b1);
            }
        }
        // mma consumed the loaded regs -> stage reads complete; release it
        MBAR_ARRIVE(sb + MB_OFF + 24 + 8 * s);
    }

    // warps may be skewed; T aliases stages 0/1 -> barrier before overwrite
    __syncthreads();

    // ---- T (f16) into alias region ----
    {
        const int cb = pbase + (lane & 3) * 2;
#pragma unroll
        for (int m = 0; m < 2; m++) {
            const int r0 = abase + m * 16 + (lane >> 2);
#pragma unroll
            for (int t = 0; t < 7; t++) {
                int c = cb + t * 8;
                asm volatile("st.shared.b32 [%0], %1;"
                    :: "r"(sb + OFF_TS + (r0 * TPITCH + c) * 2), "r"(f2h2(acc[m][t][0], acc[m][t][1])) : "memory");
                asm volatile("st.shared.b32 [%0], %1;"
                    :: "r"(sb + OFF_TS + ((r0 + 8) * TPITCH + c) * 2), "r"(f2h2(acc[m][t][2], acc[m][t][3])) : "memory");
            }
        }
    }
    // Bs[h][p] f16, pads zero
    for (int i = tid; i < 64 * PP; i += 256) {
        int p = i >> 6, h = i & 63;
        float v = (p < P_DIM) ? Bmat[p * 64 + h] : 0.0f;
        unsigned short hb = __half_as_ushort(__float2half_rn(v));
        asm volatile("st.shared.b16 [%0], %1;"
            :: "r"(sb + OFF_BS + (h * TPITCH + p) * 2), "h"(hb) : "memory");
    }
    __syncthreads();

    // ---- G2: out[a,h] = sum_p T[a,p] Bs[h,p], K = 224, fp16 ----
    float o[4][4];
#pragma unroll
    for (int i = 0; i < 4; i++)
        o[i][0] = o[i][1] = o[i][2] = o[i][3] = 0.0f;
    const uint32_t tsb = sb + OFF_TS;
    const uint32_t bsb = sb + OFF_BS;
    const int a2row = (wid >> 1) * 16 + (lane & 15);
    const int a2co = (lane & 16) ? 8 : 0;
    const int hhalf = (wid & 1) * 32;
    const int browofs = (lane & 7) + ((lane & 16) >> 1);
    const int bcolofs = ((lane >> 3) & 1) * 8;
#pragma unroll
    for (int ks = 0; ks < 14; ks++) {
        const int k0 = ks * 16;
        uint32_t a[4];
        ldsm4(a, tsb + (a2row * TPITCH + k0 + a2co) * 2);
#pragma unroll
        for (int g = 0; g < 2; g++) {
            uint32_t b[4];
            ldsm4(b, bsb + ((hhalf + g * 16 + browofs) * TPITCH + k0 + bcolofs) * 2);
            mma16816(o[2 * g], a[0], a[1], a[2], a[3], b[0], b[1]);
            mma16816(o[2 * g + 1], a[0], a[1], a[2], a[3], b[2], b[3]);
        }
    }
    {
        float* ob = out + (size_t)bn * 4096;
        const int r0 = (wid >> 1) * 16 + lane / 4;
        const int cb = hhalf + (lane & 3) * 2;
#pragma unroll
        for (int nt = 0; nt < 4; nt++) {
            int c = cb + nt * 8;
            *reinterpret_cast<float2*>(ob + r0 * 64 + c) = make_float2(o[nt][0], o[nt][1]);
            *reinterpret_cast<float2*>(ob + (r0 + 8) * 64 + c) = make_float2(o[nt][2], o[nt][3]);
        }
    }
}

extern "C" void kernel_launch(void* const* d_in, const int* in_sizes, int n_in,
                              void* d_out, int out_size) {
    int ix = 0, ia = 1, ib = 2;
    for (int i = 0; i < n_in; i++) {
        if (in_sizes[i] == 237244416) ix = i;
        else if (in_sizes[i] == 49152) ia = i;
        else if (in_sizes[i] == 12544) ib = i;
    }
    void* xp = d_in[ix];
    const float* A = (const float*)d_in[ia];
    const float* B = (const float*)d_in[ib];
    float* out = (float*)d_out;

    void* ah_ptr = nullptr;
    cudaGetSymbolAddress(&ah_ptr, g_Ah);

    typedef CUresult (CUDAAPI * EncFn)(
        CUtensorMap*, CUtensorMapDataType, cuuint32_t, void*,
        const cuuint64_t*, const cuuint64_t*, const cuuint32_t*, const cuuint32_t*,
        CUtensorMapInterleave, CUtensorMapSwizzle, CUtensorMapL2promotion, CUtensorMapFloatOOBfill);
    void* fnp = nullptr;
    cudaDriverEntryPointQueryResult qr;
    cudaGetDriverEntryPointByVersion("cuTensorMapEncodeTiled", &fnp, 12000,
                                     cudaEnableDefault, &qr);
    EncFn enc = (EncFn)fnp;

    CUtensorMap tmX, tmA;
    {
        cuuint64_t dims[3] = { (cuuint64_t)C_DIM, (cuuint64_t)P_DIM, 1576 };
        cuuint64_t strides[2] = { (cuuint64_t)C_DIM * 4, (cuuint64_t)P_DIM * C_DIM * 4 };
        cuuint32_t box[3] = { 32, (cuuint32_t)P_DIM, 1 };
        cuuint32_t es[3] = { 1, 1, 1 };
        enc(&tmX, CU_TENSOR_MAP_DATA_TYPE_FLOAT32, 3, xp, dims, strides, box, es,
            CU_TENSOR_MAP_INTERLEAVE_NONE, CU_TENSOR_MAP_SWIZZLE_128B,
            CU_TENSOR_MAP_L2_PROMOTION_L2_128B, CU_TENSOR_MAP_FLOAT_OOB_FILL_NONE);
    }
    {
        cuuint64_t dims[2] = { (cuuint64_t)C_DIM, 64 };
        cuuint64_t strides[1] = { (cuuint64_t)C_DIM * 2 };
        cuuint32_t box[2] = { 32, 64 };
        cuuint32_t es[2] = { 1, 1 };
        enc(&tmA, CU_TENSOR_MAP_DATA_TYPE_FLOAT16, 2, ah_ptr, dims, strides, box, es,
            CU_TENSOR_MAP_INTERLEAVE_NONE, CU_TENSOR_MAP_SWIZZLE_NONE,
            CU_TENSOR_MAP_L2_PROMOTION_L2_128B, CU_TENSOR_MAP_FLOAT_OOB_FILL_NONE);
    }

    cvt_A_kernel<<<(64 * C_DIM + 255) / 256, 256>>>(A);
    cudaFuncSetAttribute(sepnet_tma_kernel,
                         cudaFuncAttributeMaxDynamicSharedMemorySize, SMEM_ALLOC);
    sepnet_tma_kernel<<<1576, 256, SMEM_ALLOC>>>(B, out, tmX, tmA);
}